// round 3
// baseline (speedup 1.0000x reference)
#include <cuda_runtime.h>

// Advect stencil, 8 outputs/thread, warp-shuffle halo exchange (zero redundant LDG
// except lane 31 of each warp).
// L = 8192 per row, output 8188. 1024 thread-slots/row (slot 1023 emits only 4).

#define ROW_L     8192
#define ROW_OUT   8188
#define SLOTS_ROW 1024
#define THETA     2.0f

__device__ __forceinline__ float minmod3(float a, float b, float c) {
    float mn = fminf(fminf(a, b), c);
    float mx = fmaxf(fmaxf(a, b), c);
    return (mn < 0.0f) ? fminf(mx, 0.0f) : mn;
}

__global__ __launch_bounds__(256)
void advect_kernel(const float* __restrict__ rho,
                   const float* __restrict__ v,
                   float* __restrict__ out) {
    const int t    = blockIdx.x * blockDim.x + threadIdx.x;   // slot in row, 0..1023
    const int row  = blockIdx.y;
    const int lane = threadIdx.x & 31;

    const float* rrho = rho + (size_t)row * ROW_L;
    const float* rv   = v   + (size_t)row * ROW_L;
    float*       rout = out + (size_t)row * ROW_OUT;

    const int  k0   = t * 8;
    const bool tail = (t == SLOTS_ROW - 1);   // last slot: only 4 outputs, no halo needed

    // Own 8 elements: 4 front-batched LDG.128
    float4 ra = *reinterpret_cast<const float4*>(rrho + k0);
    float4 va = *reinterpret_cast<const float4*>(rv   + k0);
    float4 rb = *reinterpret_cast<const float4*>(rrho + k0 + 4);
    float4 vb = *reinterpret_cast<const float4*>(rv   + k0 + 4);

    float f0 = ra.x * va.x, f1 = ra.y * va.y, f2 = ra.z * va.z, f3 = ra.w * va.w;
    float f4 = rb.x * vb.x, f5 = rb.y * vb.y, f6 = rb.z * vb.z, f7 = rb.w * vb.w;

    // Halo (elements k0+8..k0+11) from lane+1 via shuffle: its f0..f3, v.x..v.z
    float f8  = __shfl_down_sync(0xffffffffu, f0,   1);
    float f9  = __shfl_down_sync(0xffffffffu, f1,   1);
    float f10 = __shfl_down_sync(0xffffffffu, f2,   1);
    float f11 = __shfl_down_sync(0xffffffffu, f3,   1);
    float v8  = __shfl_down_sync(0xffffffffu, va.x, 1);
    float v9  = __shfl_down_sync(0xffffffffu, va.y, 1);
    float v10 = __shfl_down_sync(0xffffffffu, va.z, 1);

    // Lane 31 (except row tail): fetch halo directly
    if (lane == 31 && !tail) {
        float4 rc = *reinterpret_cast<const float4*>(rrho + k0 + 8);
        float4 vc = *reinterpret_cast<const float4*>(rv   + k0 + 8);
        f8 = rc.x * vc.x; f9 = rc.y * vc.y; f10 = rc.z * vc.z; f11 = rc.w * vc.w;
        v8 = vc.x; v9 = vc.y; v10 = vc.z;
    }

    float f[12]  = {f0, f1, f2, f3, f4, f5, f6, f7, f8, f9, f10, f11};
    float vv[11] = {va.x, va.y, va.z, va.w, vb.x, vb.y, vb.z, vb.w, v8, v9, v10};

    // half slopes hs[m] = hs_global[k0+m], m = 0..9
    float hs[10];
    #pragma unroll
    for (int i = 0; i < 10; i++) {
        float c0 = THETA * (f[i + 1] - f[i]);
        float c1 = 0.5f  * (f[i + 2] - f[i]);
        float c2 = THETA * (f[i + 2] - f[i + 1]);
        hs[i] = 0.5f * minmod3(c0, c1, c2);
    }

    // net[j] = net_global[k0+j], j = 0..8
    float net[9];
    #pragma unroll
    for (int j = 0; j < 9; j++) {
        int gj = k0 + j;
        float fm = (vv[j + 2] >= 0.0f) ? 0.0f : (f[j + 2] - hs[j + 1]);
        float fp = (vv[j + 1] <= 0.0f) ? 0.0f : (f[j + 1] + hs[j]);
        if (gj == 0)          fp = 0.0f;   // flux_plus[0] = 0
        if (gj == ROW_L - 4)  fm = 0.0f;   // flux_minus[L-4] = 0 (tail's net[4])
        net[j] = fm + fp;
    }

    float4 o0, o1;
    o0.x = net[0] - net[1];
    o0.y = net[1] - net[2];
    o0.z = net[2] - net[3];
    o0.w = net[3] - net[4];
    o1.x = net[4] - net[5];
    o1.y = net[5] - net[6];
    o1.z = net[6] - net[7];
    o1.w = net[7] - net[8];

    __stcs(reinterpret_cast<float4*>(rout + k0), o0);
    if (!tail)
        __stcs(reinterpret_cast<float4*>(rout + k0 + 4), o1);
}

extern "C" void kernel_launch(void* const* d_in, const int* in_sizes, int n_in,
                              void* d_out, int out_size) {
    const float* rho = (const float*)d_in[0];
    const float* v   = (const float*)d_in[1];
    float* out = (float*)d_out;

    int rows = in_sizes[0] / ROW_L;   // 16*256 = 4096

    dim3 block(256);
    dim3 grid(SLOTS_ROW / 256, rows);   // (4, 4096)
    advect_kernel<<<grid, block>>>(rho, v, out);
}